// round 7
// baseline (speedup 1.0000x reference)
#include <cuda_runtime.h>
#include <cuda_fp16.h>

#define NN 50000
#define EE 800000
#define DD 128
#define BN_EPS 1e-5f
#define SCAN_B 1024
#define NBLK ((NN + SCAN_B - 1) / SCAN_B)   // 49

// ---- scratch (device globals: allocation-free per harness rules) ----
__device__ float g_xw[NN * DD];      // x @ W (fp32)
__device__ uint2 g_xwh[NN * DD / 4]; // x @ W (fp16, packed 4/uint2) for gather
__device__ float g_agg[NN * DD];     // aggregated output of GCN conv
__device__ float g_dinv[NN];
__device__ int   g_degi[NN];
__device__ int   g_off[NN + 1];      // CSR offsets
__device__ int   g_cur[NN];          // fill cursors
__device__ int   g_rowi[EE];         // edge rows as int32
__device__ int   g_coli[EE];         // edge cols as int32
__device__ int   g_adj[EE];          // CSR adjacency (col indices)
__device__ int   g_bsum[NBLK];       // per-block scan totals
__device__ float g_colsum[DD];
__device__ float g_colsumsq[DD];
__device__ float g_mean[DD];
__device__ float g_scale[DD];        // gamma * rsqrt(var+eps)
__device__ int   g_is64;             // 1 if edge_index is int64, 0 if int32

// ---- K1: zero degrees + BN accums; block 0 also detects edge dtype ----
__global__ void k_init(const void* __restrict__ ei, int N) {
    __shared__ int s_bad;
    int tid = threadIdx.x;
    if (blockIdx.x == 0) {
        if (tid == 0) s_bad = 0;
        __syncthreads();
        long long v = ((const long long*)ei)[tid];
        if (v < 0 || v >= N) atomicOr(&s_bad, 1);
        __syncthreads();
        if (tid == 0) g_is64 = s_bad ? 0 : 1;
    }
    int i = blockIdx.x * blockDim.x + tid;
    if (i < N) g_degi[i] = 0;
    if (i < DD) { g_colsum[i] = 0.0f; g_colsumsq[i] = 0.0f; }
}

// ---- K2: convert edges to int32 + histogram rows ----
__global__ void k_prep(const void* __restrict__ ei, int E, int N) {
    int e = blockIdx.x * blockDim.x + threadIdx.x;
    if (e >= E) return;
    int row, col;
    if (g_is64) {
        row = (int)((const long long*)ei)[e];
        col = (int)((const long long*)ei)[E + e];
    } else {
        row = ((const int*)ei)[e];
        col = ((const int*)ei)[E + e];
    }
    if ((unsigned)row >= (unsigned)N || (unsigned)col >= (unsigned)N) {
        g_rowi[e] = -1; g_coli[e] = 0;
        return;
    }
    g_rowi[e] = row;
    g_coli[e] = col;
    atomicAdd(&g_degi[row], 1);
}

// ---- K3: per-block inclusive scan + block totals ----
__global__ __launch_bounds__(SCAN_B) void k_scan1(int N) {
    __shared__ int warp_tot[32];
    int tid = threadIdx.x;
    int lane = tid & 31, wid = tid >> 5;
    int i = blockIdx.x * SCAN_B + tid;
    int v = (i < N) ? g_degi[i] : 0;
    int s = v;
#pragma unroll
    for (int d = 1; d < 32; d <<= 1) {
        int t = __shfl_up_sync(0xffffffffu, s, d);
        if (lane >= d) s += t;
    }
    if (lane == 31) warp_tot[wid] = s;
    __syncthreads();
    if (wid == 0) {
        int t = warp_tot[lane];
        int ws = t;
#pragma unroll
        for (int d = 1; d < 32; d <<= 1) {
            int u = __shfl_up_sync(0xffffffffu, ws, d);
            if (lane >= d) ws += u;
        }
        warp_tot[lane] = ws - t;  // exclusive warp offsets
    }
    __syncthreads();
    int incl = s + warp_tot[wid];
    if (i < N) g_off[i + 1] = incl;
    if (tid == SCAN_B - 1) g_bsum[blockIdx.x] = incl;
}

// ---- K4: finalize offsets (add block prefix) + dinv + fill cursors ----
__global__ void k_post(int N) {
    int i = blockIdx.x * blockDim.x + threadIdx.x;
    if (i >= N) return;
    int chunk = i >> 10;
    int boff = 0;
    for (int b = 0; b < chunk; b++) boff += g_bsum[b];
    int incl = g_off[i + 1] + boff;
    g_off[i + 1] = incl;
    int deg = g_degi[i];
    g_cur[i] = incl - deg;
    g_dinv[i] = rsqrtf((float)(deg + 1));
    if (i == 0) g_off[0] = 0;
}

// ---- K5: CSR fill ----
__global__ void k_fill(int E) {
    int e = blockIdx.x * blockDim.x + threadIdx.x;
    if (e >= E) return;
    int row = g_rowi[e];
    if (row < 0) return;
    int pos = atomicAdd(&g_cur[row], 1);
    g_adj[pos] = g_coli[e];
}

// ---- K6: xw = x @ W; epilogue stores fp32 + packed fp16 copies ----
__global__ __launch_bounds__(256) void k_gemm(const float* __restrict__ x,
                                              const float* __restrict__ W,
                                              int N) {
    int lane = threadIdx.x & 31;
    int gw = (blockIdx.x * blockDim.x + threadIdx.x) >> 5;
    int r0 = gw * 8;
    if (r0 >= N) return;
    int rows = min(8, N - r0);

    const float4* W4 = (const float4*)W;
    const float4* x4 = (const float4*)x;

    float4 acc[8];
#pragma unroll
    for (int r = 0; r < 8; r++) acc[r] = make_float4(0.f, 0.f, 0.f, 0.f);

#pragma unroll 4
    for (int k4 = 0; k4 < 32; k4++) {
        float4 wv0 = W4[(k4 * 4 + 0) * 32 + lane];
        float4 wv1 = W4[(k4 * 4 + 1) * 32 + lane];
        float4 wv2 = W4[(k4 * 4 + 2) * 32 + lane];
        float4 wv3 = W4[(k4 * 4 + 3) * 32 + lane];
#pragma unroll
        for (int r = 0; r < 8; r++) {
            int row = r0 + r; if (row >= N) row = N - 1;
            float4 xv = x4[row * 32 + k4];
            acc[r].x = fmaf(xv.x, wv0.x, acc[r].x);
            acc[r].y = fmaf(xv.x, wv0.y, acc[r].y);
            acc[r].z = fmaf(xv.x, wv0.z, acc[r].z);
            acc[r].w = fmaf(xv.x, wv0.w, acc[r].w);
            acc[r].x = fmaf(xv.y, wv1.x, acc[r].x);
            acc[r].y = fmaf(xv.y, wv1.y, acc[r].y);
            acc[r].z = fmaf(xv.y, wv1.z, acc[r].z);
            acc[r].w = fmaf(xv.y, wv1.w, acc[r].w);
            acc[r].x = fmaf(xv.z, wv2.x, acc[r].x);
            acc[r].y = fmaf(xv.z, wv2.y, acc[r].y);
            acc[r].z = fmaf(xv.z, wv2.z, acc[r].z);
            acc[r].w = fmaf(xv.z, wv2.w, acc[r].w);
            acc[r].x = fmaf(xv.w, wv3.x, acc[r].x);
            acc[r].y = fmaf(xv.w, wv3.y, acc[r].y);
            acc[r].z = fmaf(xv.w, wv3.z, acc[r].z);
            acc[r].w = fmaf(xv.w, wv3.w, acc[r].w);
        }
    }

    float4* xw4 = (float4*)g_xw;
#pragma unroll
    for (int r = 0; r < 8; r++) {
        if (r < rows) {
            int row = r0 + r;
            xw4[row * 32 + lane] = acc[r];
            __half2 h0 = __float22half2_rn(make_float2(acc[r].x, acc[r].y));
            __half2 h1 = __float22half2_rn(make_float2(acc[r].z, acc[r].w));
            uint2 u;
            u.x = *(unsigned*)&h0;
            u.y = *(unsigned*)&h1;
            g_xwh[row * 32 + lane] = u;
        }
    }
}

// ---- K7: per-node gather from fp16 table + fused BN stats ----
// agg[n] = dinv[n] * ( xw[n]*dinv[n] + sum_{c in adj(n)} dinv[c]*xwh[c] )
__global__ __launch_bounds__(256) void k_gather(int N) {
    __shared__ float s_sum[DD], s_sq[DD];
    int tid = threadIdx.x;
    int lane = tid & 31;
    int n = (blockIdx.x * blockDim.x + tid) >> 5;
    if (tid < DD) { s_sum[tid] = 0.f; s_sq[tid] = 0.f; }
    __syncthreads();

    float4 acc = make_float4(0.f, 0.f, 0.f, 0.f);
    if (n < N) {
        int j = g_off[n], end = g_off[n + 1];
        for (; j + 2 <= end; j += 2) {            // unroll-2 for MLP
            int c0 = g_adj[j], c1 = g_adj[j + 1];
            float w0 = g_dinv[c0], w1 = g_dinv[c1];
            uint2 u0 = g_xwh[c0 * 32 + lane];
            uint2 u1 = g_xwh[c1 * 32 + lane];
            float2 a0 = __half22float2(*(__half2*)&u0.x);
            float2 b0 = __half22float2(*(__half2*)&u0.y);
            float2 a1 = __half22float2(*(__half2*)&u1.x);
            float2 b1 = __half22float2(*(__half2*)&u1.y);
            acc.x = fmaf(a0.x, w0, fmaf(a1.x, w1, acc.x));
            acc.y = fmaf(a0.y, w0, fmaf(a1.y, w1, acc.y));
            acc.z = fmaf(b0.x, w0, fmaf(b1.x, w1, acc.z));
            acc.w = fmaf(b0.y, w0, fmaf(b1.y, w1, acc.w));
        }
        if (j < end) {
            int c0 = g_adj[j];
            float w0 = g_dinv[c0];
            uint2 u0 = g_xwh[c0 * 32 + lane];
            float2 a0 = __half22float2(*(__half2*)&u0.x);
            float2 b0 = __half22float2(*(__half2*)&u0.y);
            acc.x = fmaf(a0.x, w0, acc.x);
            acc.y = fmaf(a0.y, w0, acc.y);
            acc.z = fmaf(b0.x, w0, acc.z);
            acc.w = fmaf(b0.y, w0, acc.w);
        }
        float dr = g_dinv[n];
        float4 sv = ((const float4*)g_xw)[n * 32 + lane];   // self term fp32
        acc.x = (acc.x + sv.x * dr) * dr;
        acc.y = (acc.y + sv.y * dr) * dr;
        acc.z = (acc.z + sv.z * dr) * dr;
        acc.w = (acc.w + sv.w * dr) * dr;
        ((float4*)g_agg)[n * 32 + lane] = acc;
    }

    // fused BN statistics: block-level shared reduce, then one RED per column
    int c0 = lane * 4;
    atomicAdd(&s_sum[c0 + 0], acc.x);
    atomicAdd(&s_sum[c0 + 1], acc.y);
    atomicAdd(&s_sum[c0 + 2], acc.z);
    atomicAdd(&s_sum[c0 + 3], acc.w);
    atomicAdd(&s_sq[c0 + 0], acc.x * acc.x);
    atomicAdd(&s_sq[c0 + 1], acc.y * acc.y);
    atomicAdd(&s_sq[c0 + 2], acc.z * acc.z);
    atomicAdd(&s_sq[c0 + 3], acc.w * acc.w);
    __syncthreads();
    if (tid < DD) atomicAdd(&g_colsum[tid], s_sum[tid]);
    else if (tid < 2 * DD) atomicAdd(&g_colsumsq[tid - DD], s_sq[tid - DD]);
}

// ---- K9: finalize BN params (bias b cancels through mean subtraction) ----
__global__ void k_bnparam(const float* __restrict__ gamma, float nInv) {
    int c = threadIdx.x;
    float mean = g_colsum[c] * nInv;
    float var = g_colsumsq[c] * nInv - mean * mean;
    g_mean[c] = mean;
    g_scale[c] = rsqrtf(var + BN_EPS) * gamma[c];
}

// ---- K10: y = relu((agg - mean)*scale + beta) + x ----
__global__ void k_final(const float* __restrict__ x, const float* __restrict__ beta,
                        float* __restrict__ out, int n4) {
    int t = blockIdx.x * blockDim.x + threadIdx.x;
    if (t >= n4) return;
    int cb = t & 31;
    float4 a  = ((const float4*)g_agg)[t];
    float4 xr = ((const float4*)x)[t];
    float4 m  = ((const float4*)g_mean)[cb];
    float4 s  = ((const float4*)g_scale)[cb];
    float4 bt = ((const float4*)beta)[cb];
    float4 r;
    r.x = fmaxf((a.x - m.x) * s.x + bt.x, 0.f) + xr.x;
    r.y = fmaxf((a.y - m.y) * s.y + bt.y, 0.f) + xr.y;
    r.z = fmaxf((a.z - m.z) * s.z + bt.z, 0.f) + xr.z;
    r.w = fmaxf((a.w - m.w) * s.w + bt.w, 0.f) + xr.w;
    ((float4*)out)[t] = r;
}

extern "C" void kernel_launch(void* const* d_in, const int* in_sizes, int n_in,
                              void* d_out, int out_size) {
    const float* x     = (const float*)d_in[0];
    const void*  ei    = d_in[1];
    const float* W     = (const float*)d_in[2];
    // d_in[3] = b — cancels exactly through BatchNorm, unused
    const float* gamma = (const float*)d_in[4];
    const float* beta  = (const float*)d_in[5];
    float*       out   = (float*)d_out;

    int N = in_sizes[0] / DD;
    int E = in_sizes[1] / 2;
    int nblk = (N + SCAN_B - 1) / SCAN_B;

    static cudaStream_t s2 = nullptr;
    static cudaEvent_t ev_fork = nullptr, ev_join = nullptr;
    if (s2 == nullptr) {
        cudaStreamCreateWithFlags(&s2, cudaStreamNonBlocking);
        cudaEventCreateWithFlags(&ev_fork, cudaEventDisableTiming);
        cudaEventCreateWithFlags(&ev_join, cudaEventDisableTiming);
    }

    // ---- fork: GEMM (x,W only) runs concurrently with the CSR build ----
    cudaEventRecord(ev_fork, 0);
    cudaStreamWaitEvent(s2, ev_fork, 0);
    int gwarps = (N + 7) / 8;
    k_gemm<<<(gwarps + 7) / 8, 256, 0, s2>>>(x, W, N);
    cudaEventRecord(ev_join, s2);

    // ---- CSR build chain on the main stream ----
    k_init<<<(N + 255) / 256, 256>>>(ei, N);
    k_prep<<<(E + 255) / 256, 256>>>(ei, E, N);
    k_scan1<<<nblk, SCAN_B>>>(N);
    k_post<<<(N + 255) / 256, 256>>>(N);
    k_fill<<<(E + 255) / 256, 256>>>(E);

    // ---- join, then aggregate (+fused BN stats) ----
    cudaStreamWaitEvent(0, ev_join, 0);
    k_gather<<<(N + 7) / 8, 256>>>(N);

    k_bnparam<<<1, DD>>>(gamma, 1.0f / (float)N);

    int n4 = N * (DD / 4);
    k_final<<<(n4 + 255) / 256, 256>>>(x, beta, out, n4);
}